// round 13
// baseline (speedup 1.0000x reference)
#include <cuda_runtime.h>
#include <math.h>

#define PP 3
#define NN 50000
#define EE 256000
#define CC 5
#define FF 68
#define FE 16
#define FN 64
#define F2 (2*FF)   // 136
#define SLOTS 32

typedef unsigned int uint;

__device__ __forceinline__ float tanh_fast(float x) {
    float y; asm("tanh.approx.f32 %0, %1;" : "=f"(y) : "f"(x)); return y;
}
__device__ __forceinline__ uint f2tf32(float v) {
    uint t; asm("cvt.rna.tf32.f32 %0, %1;" : "=r"(t) : "f"(v)); return t;
}
__device__ __forceinline__ void mma_tf32(float* c, const uint* a, uint b0, uint b1) {
    asm volatile("mma.sync.aligned.m16n8k8.row.col.f32.tf32.tf32.f32 "
        "{%0,%1,%2,%3}, {%4,%5,%6,%7}, {%8,%9}, {%0,%1,%2,%3};"
        : "+f"(c[0]), "+f"(c[1]), "+f"(c[2]), "+f"(c[3])
        : "r"(a[0]), "r"(a[1]), "r"(a[2]), "r"(a[3]), "r"(b0), "r"(b1));
}

// Scratch
__device__ __align__(16) float g_A[(size_t)PP*NN*CC*FE];         // 48 MB
__device__ __align__(16) float g_B[(size_t)PP*NN*CC*FE];         // 48 MB
__device__ __align__(16) float g_P[(size_t)PP*NN*CC*FN];         // 192 MB
__device__ __align__(16) float g_Y[(size_t)PP*NN*CC*FN];         // 192 MB
__device__ __align__(16) float g_bkt[(size_t)PP*NN*SLOTS*8];     // 154 MB
__device__ int g_deg[PP*NN];
// Pre-transposed, tf32, k-interleaved weights
__device__ __align__(16) uint g_W1t[(size_t)PP*CC*160*72];
__device__ __align__(16) uint g_W2t[(size_t)PP*CC*64*64];

__global__ void zero_deg_kernel() {
    const int i = blockIdx.x*blockDim.x + threadIdx.x;
    if (i < PP*NN) g_deg[i] = 0;
}

// ---------------------------------------------------------------------------
// wprep: fused+transposed tf32 weight images, k-interleaved (k0,k4,k1,k5,...)
// ---------------------------------------------------------------------------
__global__ __launch_bounds__(256) void wprep_kernel(
    const float* __restrict__ We1, const float* __restrict__ Wn1,
    const float* __restrict__ Wn2)
{
    const int pc = blockIdx.x;
    const size_t eoff = (size_t)pc*FE*F2;
    const size_t noff = (size_t)pc*FN*F2;

    uint* w1 = g_W1t + (size_t)pc*160*72;
    for (int i = threadIdx.x; i < 160*72; i += blockDim.x) {
        const int g = i / 72, kp = i % 72;
        const int ks = kp >> 3, pos = kp & 7;
        const int k = ks*8 + (pos >> 1) + (pos & 1)*4;
        float v = 0.f;
        if (k < FF) {
            if (g < 16)      v = We1[eoff + (size_t)g*F2 + k];
            else if (g < 32) v = We1[eoff + (size_t)(g-16)*F2 + FF + k];
            else if (g < 96) v = Wn1[noff + (size_t)(g-32)*F2 + k];
            else             v = Wn1[noff + (size_t)(g-96)*F2 + FF + k];
        }
        w1[i] = f2tf32(v);
    }

    uint* w2 = g_W2t + (size_t)pc*64*64;
    const float* Wn2p = Wn2 + (size_t)pc*FN*FN;
    for (int i = threadIdx.x; i < 64*64; i += blockDim.x) {
        const int g = i >> 6, kp = i & 63;
        const int ks = kp >> 3, pos = kp & 7;
        const int k = ks*8 + (pos >> 1) + (pos & 1)*4;
        w2[i] = f2tf32(Wn2p[(size_t)g*FN + k]);
    }
}

// ---------------------------------------------------------------------------
// G1: [A|B|P|Y](160) = x(68) . Wf^T per (p,c), tf32 MMA. 128 nodes/block.
// ---------------------------------------------------------------------------
#define XST 76
#define WST 76

__global__ __launch_bounds__(256, 2) void g1_kernel(
    const float* __restrict__ x,
    const float* __restrict__ be1, const float* __restrict__ bn1)
{
    extern __shared__ __align__(16) uint smem_u[];
    uint*  XS    = smem_u;
    uint*  WS    = XS + 128*XST;
    float* sbias = (float*)(WS + 160*WST);

    const int c = blockIdx.y, p = blockIdx.z, tid = threadIdx.x;
    const int n0 = blockIdx.x * 128;
    const int pc = p*CC + c;

    const uint* w1 = g_W1t + (size_t)pc*160*72;
    for (int i = tid; i < 160*18; i += 256) {
        const int g = i / 18, j = i % 18;
        *(uint4*)&WS[g*WST + j*4] = *(const uint4*)&w1[g*72 + j*4];
    }
    for (int g = tid; g < 160; g += 256) {
        float b = 0.f;
        if (g < 16)                 b = be1[pc*FE + g];
        else if (g >= 32 && g < 96) b = bn1[pc*FN + (g-32)];
        sbias[g] = b;
    }
    for (int i = tid; i < 128*17; i += 256) {
        const int r = i / 17, f4 = i % 17;
        const int n = n0 + r;
        float4 v = make_float4(0.f, 0.f, 0.f, 0.f);
        if (n < NN)
            v = *(const float4*)(x + (((size_t)p*NN + n)*CC + c)*FF + f4*4);
        const int ks = f4 >> 1;
        uint* b = &XS[r*XST + ks*8 + (f4 & 1)];
        b[0] = f2tf32(v.x); b[2] = f2tf32(v.y);
        b[4] = f2tf32(v.z); b[6] = f2tf32(v.w);
    }
    for (int i = tid; i < 128*4; i += 256) {
        const int r = i >> 2, j = i & 3;
        XS[r*XST + 64 + 2*j + 1] = 0;
    }
    __syncthreads();

    const int warp = tid >> 5, lane = tid & 31;
    const int rowBase = (warp & 3) * 32;
    const int colBase = (warp >> 2) * 80;
    const int r  = lane >> 2;
    const int kk = lane & 3;

    float acc[2][10][4];
    #pragma unroll
    for (int mt = 0; mt < 2; ++mt)
        #pragma unroll
        for (int nt = 0; nt < 10; ++nt)
            #pragma unroll
            for (int q = 0; q < 4; ++q) acc[mt][nt][q] = 0.f;

    #pragma unroll 1
    for (int ks = 0; ks < 9; ++ks) {
        uint a[2][4];
        #pragma unroll
        for (int mt = 0; mt < 2; ++mt) {
            const int rb = rowBase + mt*16;
            const uint2 lo = *(const uint2*)&XS[(rb + r    )*XST + ks*8 + 2*kk];
            const uint2 hi = *(const uint2*)&XS[(rb + r + 8)*XST + ks*8 + 2*kk];
            a[mt][0] = lo.x; a[mt][1] = hi.x; a[mt][2] = lo.y; a[mt][3] = hi.y;
        }
        #pragma unroll
        for (int nt = 0; nt < 10; ++nt) {
            const uint2 b = *(const uint2*)&WS[(colBase + nt*8 + r)*WST + ks*8 + 2*kk];
            mma_tf32(acc[0][nt], a[0], b.x, b.y);
            mma_tf32(acc[1][nt], a[1], b.x, b.y);
        }
    }

    const size_t pnc = (size_t)p*NN;
    #pragma unroll
    for (int mt = 0; mt < 2; ++mt) {
        #pragma unroll
        for (int half = 0; half < 2; ++half) {
            const int n = n0 + rowBase + mt*16 + r + half*8;
            if (n >= NN) continue;
            const size_t base = (pnc + n)*CC + c;
            #pragma unroll
            for (int nt = 0; nt < 10; ++nt) {
                const int g = colBase + nt*8 + kk*2;
                float2 v;
                v.x = acc[mt][nt][half*2 + 0] + sbias[g];
                v.y = acc[mt][nt][half*2 + 1] + sbias[g+1];
                if (g < 16)      *(float2*)(g_A + base*FE + g)      = v;
                else if (g < 32) *(float2*)(g_B + base*FE + (g-16)) = v;
                else if (g < 96) *(float2*)(g_P + base*FN + (g-32)) = v;
                else             *(float2*)(g_Y + base*FN + (g-96)) = v;
            }
        }
    }
}

// ---------------------------------------------------------------------------
// gate: per edge, compute softmax class weights; write one 32B bucket record
// {src, w0..w4} into dst's slot list.
// ---------------------------------------------------------------------------
__global__ __launch_bounds__(256) void gate_kernel(
    const void* __restrict__ ei,
    const float* __restrict__ We2, const float* __restrict__ be2)
{
    __shared__ float sW2[CC*FE];
    __shared__ float sb2[CC];

    const int p = blockIdx.y;
    for (int i = threadIdx.x; i < CC*FE; i += blockDim.x)
        sW2[i] = We2[p*CC*FE + i];
    if (threadIdx.x < CC) sb2[threadIdx.x] = be2[p*CC + threadIdx.x];
    __syncthreads();

    const long long* q = (const long long*)ei;
    int ok = 1;
    #pragma unroll
    for (int i = 0; i < 16; ++i) {
        const long long v = q[i];
        ok &= (v >= 0) && (v < NN);
    }

    const long long* ei64 = (const long long*)ei;
    const int*       ei32 = (const int*)ei;
    const size_t base = (size_t)p*2*EE;

    const int e = blockIdx.x*blockDim.x + threadIdx.x;
    int s, d;
    if (ok) {
        s = (int)ei64[base + e];
        d = (int)ei64[base + EE + e];
    } else {
        s = ei32[base + e];
        d = ei32[base + EE + e];
    }

    const float4* Ad = (const float4*)(g_A + ((size_t)p*NN + d)*(CC*FE));
    const float4* Bs = (const float4*)(g_B + ((size_t)p*NN + s)*(CC*FE));

    float lg[CC];
    #pragma unroll
    for (int c = 0; c < CC; ++c) {
        float l = sb2[c];
        #pragma unroll
        for (int j = 0; j < 4; ++j) {
            const float4 a = Ad[c*4 + j];
            const float4 b = Bs[c*4 + j];
            l += tanh_fast(a.x + b.x) * sW2[c*FE + 4*j + 0]
               + tanh_fast(a.y + b.y) * sW2[c*FE + 4*j + 1]
               + tanh_fast(a.z + b.z) * sW2[c*FE + 4*j + 2]
               + tanh_fast(a.w + b.w) * sW2[c*FE + 4*j + 3];
        }
        lg[c] = l;
    }

    float mx = lg[0];
    #pragma unroll
    for (int c = 1; c < CC; ++c) mx = fmaxf(mx, lg[c]);
    float w[CC];
    float sum = 0.f;
    #pragma unroll
    for (int c = 0; c < CC; ++c) { w[c] = expf(lg[c] - mx); sum += w[c]; }
    const float inv = 1.f / sum;

    const int slot = atomicAdd(&g_deg[p*NN + d], 1);
    if (slot < SLOTS) {
        float* rec = g_bkt + ((size_t)(p*NN + d)*SLOTS + slot)*8;
        *(float4*)(rec)     = make_float4(__int_as_float(s),
                                          w[0]*inv, w[1]*inv, w[2]*inv);
        *(float4*)(rec + 4) = make_float4(w[3]*inv, w[4]*inv, 0.f, 0.f);
    }
}

// ---------------------------------------------------------------------------
// G2 (fused aggregation + layer 2):
// Staging computes h = tanh(P + sum_e w*Y[src]) inline -> tf32 smem,
// then out = tanh(h . W2^T + b2) via tf32 MMA. 128 nodes x 1 class per block.
// ---------------------------------------------------------------------------
#define HST 68
#define W2T 68

__global__ __launch_bounds__(256, 2) void g2_kernel(
    const float* __restrict__ bn2, float* __restrict__ out)
{
    extern __shared__ __align__(16) uint smem_u[];
    uint*  HS  = smem_u;
    uint*  W2S = HS + 128*HST;
    float* sb2 = (float*)(W2S + 64*W2T);

    const int c = blockIdx.y, p = blockIdx.z, tid = threadIdx.x;
    const int n0 = blockIdx.x * 128;
    const int pc = p*CC + c;

    const uint* w2 = g_W2t + (size_t)pc*64*64;
    for (int i = tid; i < 64*16; i += 256) {
        const int g = i >> 4, j = i & 15;
        *(uint4*)&W2S[g*W2T + j*4] = *(const uint4*)&w2[g*64 + j*4];
    }
    if (tid < FN) sb2[tid] = bn2[pc*FN + tid];

    // ---- fused aggregation + tanh + tf32 conversion into HS ----
    for (int i = tid; i < 128*16; i += 256) {
        const int r = i >> 4, f4 = i & 15;
        const int n = n0 + r;
        float4 acc = make_float4(0.f, 0.f, 0.f, 0.f);
        if (n < NN) {
            const size_t pbase = (((size_t)p*NN + n)*CC + c)*FN + f4*4;
            acc = *(const float4*)(g_P + pbase);

            const int deg = min(g_deg[p*NN + n], SLOTS);
            const float4* rec = (const float4*)(g_bkt + (size_t)(p*NN + n)*SLOTS*8);
            for (int e = 0; e < deg; ++e) {
                const float4 r0 = rec[2*e];
                const int src = __float_as_int(r0.x);
                float wv;
                if (c == 0)      wv = r0.y;
                else if (c == 1) wv = r0.z;
                else if (c == 2) wv = r0.w;
                else {
                    const float4 r1 = rec[2*e + 1];
                    wv = (c == 3) ? r1.x : r1.y;
                }
                const float4 y = *(const float4*)(
                    g_Y + (((size_t)p*NN + src)*CC + c)*FN + f4*4);
                acc.x += wv*y.x; acc.y += wv*y.y;
                acc.z += wv*y.z; acc.w += wv*y.w;
            }
        }
        const int ks = f4 >> 1;
        uint* b = &HS[r*HST + ks*8 + (f4 & 1)];
        b[0] = f2tf32(tanh_fast(acc.x));
        b[2] = f2tf32(tanh_fast(acc.y));
        b[4] = f2tf32(tanh_fast(acc.z));
        b[6] = f2tf32(tanh_fast(acc.w));
    }
    __syncthreads();

    const int warp = tid >> 5, lane = tid & 31;
    const int rowBase = (warp & 3) * 32;
    const int colBase = (warp >> 2) * 32;
    const int r  = lane >> 2;
    const int kk = lane & 3;

    float acc[2][4][4];
    #pragma unroll
    for (int mt = 0; mt < 2; ++mt)
        #pragma unroll
        for (int nt = 0; nt < 4; ++nt)
            #pragma unroll
            for (int q = 0; q < 4; ++q) acc[mt][nt][q] = 0.f;

    #pragma unroll 1
    for (int ks = 0; ks < 8; ++ks) {
        uint a[2][4];
        #pragma unroll
        for (int mt = 0; mt < 2; ++mt) {
            const int rb = rowBase + mt*16;
            const uint2 lo = *(const uint2*)&HS[(rb + r    )*HST + ks*8 + 2*kk];
            const uint2 hi = *(const uint2*)&HS[(rb + r + 8)*HST + ks*8 + 2*kk];
            a[mt][0] = lo.x; a[mt][1] = hi.x; a[mt][2] = lo.y; a[mt][3] = hi.y;
        }
        #pragma unroll
        for (int nt = 0; nt < 4; ++nt) {
            const uint2 b = *(const uint2*)&W2S[(colBase + nt*8 + r)*W2T + ks*8 + 2*kk];
            mma_tf32(acc[0][nt], a[0], b.x, b.y);
            mma_tf32(acc[1][nt], a[1], b.x, b.y);
        }
    }

    #pragma unroll
    for (int mt = 0; mt < 2; ++mt) {
        #pragma unroll
        for (int half = 0; half < 2; ++half) {
            const int n = n0 + rowBase + mt*16 + r + half*8;
            if (n >= NN) continue;
            float* op = out + (((size_t)p*NN + n)*CC + c)*FN;
            #pragma unroll
            for (int nt = 0; nt < 4; ++nt) {
                const int g = colBase + nt*8 + kk*2;
                float2 v;
                v.x = tanhf(acc[mt][nt][half*2 + 0] + sb2[g]);
                v.y = tanhf(acc[mt][nt][half*2 + 1] + sb2[g+1]);
                *(float2*)(op + g) = v;
            }
        }
    }
}

extern "C" void kernel_launch(void* const* d_in, const int* in_sizes, int n_in,
                              void* d_out, int out_size) {
    const float* x   = (const float*)d_in[0];
    const void*  ei  = d_in[1];
    const float* We1 = (const float*)d_in[2];
    const float* be1 = (const float*)d_in[3];
    const float* We2 = (const float*)d_in[4];
    const float* be2 = (const float*)d_in[5];
    const float* Wn1 = (const float*)d_in[6];
    const float* bn1 = (const float*)d_in[7];
    const float* Wn2 = (const float*)d_in[8];
    const float* bn2 = (const float*)d_in[9];
    float* out = (float*)d_out;

    const int smem1 = (128*XST + 160*WST)*4 + 160*4;   // 88192 B
    const int smem2 = (128*HST + 64*W2T)*4 + 64*4;     // 52480 B
    cudaFuncSetAttribute(g1_kernel,
                         cudaFuncAttributeMaxDynamicSharedMemorySize, smem1);
    cudaFuncSetAttribute(g2_kernel,
                         cudaFuncAttributeMaxDynamicSharedMemorySize, smem2);

    wprep_kernel<<<PP*CC, 256>>>(We1, Wn1, Wn2);
    zero_deg_kernel<<<(PP*NN + 255)/256, 256>>>();

    dim3 gg((NN + 127)/128, CC, PP);
    g1_kernel<<<gg, 256, smem1>>>(x, be1, bn1);

    dim3 ge(EE/256, PP);
    gate_kernel<<<ge, 256>>>(ei, We2, be2);

    g2_kernel<<<gg, 256, smem2>>>(bn2, out);
}

// round 14
// speedup vs baseline: 1.0204x; 1.0204x over previous
#include <cuda_runtime.h>
#include <math.h>

#define PP 3
#define NN 50000
#define EE 256000
#define CC 5
#define FF 68
#define FE 16
#define FN 64
#define F2 (2*FF)   // 136
#define SLOTS 32

typedef unsigned int uint;

__device__ __forceinline__ float tanh_fast(float x) {
    float y; asm("tanh.approx.f32 %0, %1;" : "=f"(y) : "f"(x)); return y;
}
__device__ __forceinline__ uint f2tf32(float v) {
    uint t; asm("cvt.rna.tf32.f32 %0, %1;" : "=r"(t) : "f"(v)); return t;
}
__device__ __forceinline__ void mma_tf32(float* c, const uint* a, uint b0, uint b1) {
    asm volatile("mma.sync.aligned.m16n8k8.row.col.f32.tf32.tf32.f32 "
        "{%0,%1,%2,%3}, {%4,%5,%6,%7}, {%8,%9}, {%0,%1,%2,%3};"
        : "+f"(c[0]), "+f"(c[1]), "+f"(c[2]), "+f"(c[3])
        : "r"(a[0]), "r"(a[1]), "r"(a[2]), "r"(a[3]), "r"(b0), "r"(b1));
}

// Scratch
__device__ __align__(16) float g_A[(size_t)PP*NN*CC*FE];         // 48 MB
__device__ __align__(16) float g_B[(size_t)PP*NN*CC*FE];         // 48 MB
__device__ __align__(16) float g_P[(size_t)PP*NN*CC*FN];         // 192 MB
__device__ __align__(16) float g_Y[(size_t)PP*NN*CC*FN];         // 192 MB
__device__ __align__(16) uint  g_H[(size_t)PP*NN*CC*FN];         // 192 MB (tf32)
__device__ __align__(16) float g_bkt[(size_t)PP*NN*SLOTS*8];     // 154 MB
__device__ int g_deg[PP*NN];
// Pre-transposed, tf32, k-interleaved weights
__device__ __align__(16) uint g_W1t[(size_t)PP*CC*160*72];
__device__ __align__(16) uint g_W2t[(size_t)PP*CC*64*64];

__global__ void zero_deg_kernel() {
    const int i = blockIdx.x*blockDim.x + threadIdx.x;
    if (i < PP*NN) g_deg[i] = 0;
}

// ---------------------------------------------------------------------------
// wprep: fused+transposed tf32 weight images, k-interleaved (k0,k4,k1,k5,...)
// ---------------------------------------------------------------------------
__global__ __launch_bounds__(256) void wprep_kernel(
    const float* __restrict__ We1, const float* __restrict__ Wn1,
    const float* __restrict__ Wn2)
{
    const int pc = blockIdx.x;
    const size_t eoff = (size_t)pc*FE*F2;
    const size_t noff = (size_t)pc*FN*F2;

    uint* w1 = g_W1t + (size_t)pc*160*72;
    for (int i = threadIdx.x; i < 160*72; i += blockDim.x) {
        const int g = i / 72, kp = i % 72;
        const int ks = kp >> 3, pos = kp & 7;
        const int k = ks*8 + (pos >> 1) + (pos & 1)*4;
        float v = 0.f;
        if (k < FF) {
            if (g < 16)      v = We1[eoff + (size_t)g*F2 + k];
            else if (g < 32) v = We1[eoff + (size_t)(g-16)*F2 + FF + k];
            else if (g < 96) v = Wn1[noff + (size_t)(g-32)*F2 + k];
            else             v = Wn1[noff + (size_t)(g-96)*F2 + FF + k];
        }
        w1[i] = f2tf32(v);
    }

    uint* w2 = g_W2t + (size_t)pc*64*64;
    const float* Wn2p = Wn2 + (size_t)pc*FN*FN;
    for (int i = threadIdx.x; i < 64*64; i += blockDim.x) {
        const int g = i >> 6, kp = i & 63;
        const int ks = kp >> 3, pos = kp & 7;
        const int k = ks*8 + (pos >> 1) + (pos & 1)*4;
        w2[i] = f2tf32(Wn2p[(size_t)g*FN + k]);
    }
}

// ---------------------------------------------------------------------------
// G1: [A|B|P|Y](160) = x(68) . Wf^T per (p,c), tf32 MMA. 128 nodes/block.
// Writeback staged through smem (reusing XS/WS) -> coalesced float4 stores.
// ---------------------------------------------------------------------------
#define XST 76
#define WST 76
#define OST 164   // output stage stride (floats): 164%32=4 -> bank-shift/row

__global__ __launch_bounds__(256, 2) void g1_kernel(
    const float* __restrict__ x,
    const float* __restrict__ be1, const float* __restrict__ bn1)
{
    extern __shared__ __align__(16) uint smem_u[];
    uint*  XS    = smem_u;                   // 128*76
    uint*  WS    = XS + 128*XST;             // 160*76
    float* sbias = (float*)(WS + 160*WST);   // 160 (beyond stage region)
    float* stage = (float*)smem_u;           // [128][OST] = 20992 < 21888

    const int c = blockIdx.y, p = blockIdx.z, tid = threadIdx.x;
    const int n0 = blockIdx.x * 128;
    const int pc = p*CC + c;

    const uint* w1 = g_W1t + (size_t)pc*160*72;
    for (int i = tid; i < 160*18; i += 256) {
        const int g = i / 18, j = i % 18;
        *(uint4*)&WS[g*WST + j*4] = *(const uint4*)&w1[g*72 + j*4];
    }
    for (int g = tid; g < 160; g += 256) {
        float b = 0.f;
        if (g < 16)                 b = be1[pc*FE + g];
        else if (g >= 32 && g < 96) b = bn1[pc*FN + (g-32)];
        sbias[g] = b;
    }
    for (int i = tid; i < 128*17; i += 256) {
        const int r = i / 17, f4 = i % 17;
        const int n = n0 + r;
        float4 v = make_float4(0.f, 0.f, 0.f, 0.f);
        if (n < NN)
            v = *(const float4*)(x + (((size_t)p*NN + n)*CC + c)*FF + f4*4);
        const int ks = f4 >> 1;
        uint* b = &XS[r*XST + ks*8 + (f4 & 1)];
        b[0] = f2tf32(v.x); b[2] = f2tf32(v.y);
        b[4] = f2tf32(v.z); b[6] = f2tf32(v.w);
    }
    for (int i = tid; i < 128*4; i += 256) {
        const int r = i >> 2, j = i & 3;
        XS[r*XST + 64 + 2*j + 1] = 0;
    }
    __syncthreads();

    const int warp = tid >> 5, lane = tid & 31;
    const int rowBase = (warp & 3) * 32;
    const int colBase = (warp >> 2) * 80;
    const int r  = lane >> 2;
    const int kk = lane & 3;

    float acc[2][10][4];
    #pragma unroll
    for (int mt = 0; mt < 2; ++mt)
        #pragma unroll
        for (int nt = 0; nt < 10; ++nt)
            #pragma unroll
            for (int q = 0; q < 4; ++q) acc[mt][nt][q] = 0.f;

    #pragma unroll 1
    for (int ks = 0; ks < 9; ++ks) {
        uint a[2][4];
        #pragma unroll
        for (int mt = 0; mt < 2; ++mt) {
            const int rb = rowBase + mt*16;
            const uint2 lo = *(const uint2*)&XS[(rb + r    )*XST + ks*8 + 2*kk];
            const uint2 hi = *(const uint2*)&XS[(rb + r + 8)*XST + ks*8 + 2*kk];
            a[mt][0] = lo.x; a[mt][1] = hi.x; a[mt][2] = lo.y; a[mt][3] = hi.y;
        }
        #pragma unroll
        for (int nt = 0; nt < 10; ++nt) {
            const uint2 b = *(const uint2*)&WS[(colBase + nt*8 + r)*WST + ks*8 + 2*kk];
            mma_tf32(acc[0][nt], a[0], b.x, b.y);
            mma_tf32(acc[1][nt], a[1], b.x, b.y);
        }
    }
    __syncthreads();   // all warps done reading XS/WS; safe to overwrite

    // ---- stage outputs (+bias) into smem, bank-shifted rows ----
    #pragma unroll
    for (int mt = 0; mt < 2; ++mt) {
        #pragma unroll
        for (int half = 0; half < 2; ++half) {
            const int rl = rowBase + mt*16 + r + half*8;
            #pragma unroll
            for (int nt = 0; nt < 10; ++nt) {
                const int g = colBase + nt*8 + kk*2;
                float2 v;
                v.x = acc[mt][nt][half*2 + 0] + sbias[g];
                v.y = acc[mt][nt][half*2 + 1] + sbias[g+1];
                *(float2*)&stage[rl*OST + g] = v;
            }
        }
    }
    __syncthreads();

    // ---- coalesced writeback: 40 float4 chunks per row ----
    const size_t pnc = (size_t)p*NN;
    for (int i = tid; i < 128*40; i += 256) {
        const int rl = i / 40, q = i % 40;
        const int n = n0 + rl;
        if (n >= NN) continue;
        const size_t base = (pnc + n)*CC + c;
        const float4 v = *(const float4*)&stage[rl*OST + q*4];
        if (q < 4)       *(float4*)(g_A + base*FE + q*4)        = v;
        else if (q < 8)  *(float4*)(g_B + base*FE + (q-4)*4)    = v;
        else if (q < 24) *(float4*)(g_P + base*FN + (q-8)*4)    = v;
        else             *(float4*)(g_Y + base*FN + (q-24)*4)   = v;
    }
}

// ---------------------------------------------------------------------------
// gate: per edge, compute softmax class weights; write one 32B bucket record
// {src, w0..w4} into dst's slot list.
// ---------------------------------------------------------------------------
__global__ __launch_bounds__(256) void gate_kernel(
    const void* __restrict__ ei,
    const float* __restrict__ We2, const float* __restrict__ be2)
{
    __shared__ float sW2[CC*FE];
    __shared__ float sb2[CC];

    const int p = blockIdx.y;
    for (int i = threadIdx.x; i < CC*FE; i += blockDim.x)
        sW2[i] = We2[p*CC*FE + i];
    if (threadIdx.x < CC) sb2[threadIdx.x] = be2[p*CC + threadIdx.x];
    __syncthreads();

    const long long* q = (const long long*)ei;
    int ok = 1;
    #pragma unroll
    for (int i = 0; i < 16; ++i) {
        const long long v = q[i];
        ok &= (v >= 0) && (v < NN);
    }

    const long long* ei64 = (const long long*)ei;
    const int*       ei32 = (const int*)ei;
    const size_t base = (size_t)p*2*EE;

    const int e = blockIdx.x*blockDim.x + threadIdx.x;
    int s, d;
    if (ok) {
        s = (int)ei64[base + e];
        d = (int)ei64[base + EE + e];
    } else {
        s = ei32[base + e];
        d = ei32[base + EE + e];
    }

    const float4* Ad = (const float4*)(g_A + ((size_t)p*NN + d)*(CC*FE));
    const float4* Bs = (const float4*)(g_B + ((size_t)p*NN + s)*(CC*FE));

    float lg[CC];
    #pragma unroll
    for (int c = 0; c < CC; ++c) {
        float l = sb2[c];
        #pragma unroll
        for (int j = 0; j < 4; ++j) {
            const float4 a = Ad[c*4 + j];
            const float4 b = Bs[c*4 + j];
            l += tanh_fast(a.x + b.x) * sW2[c*FE + 4*j + 0]
               + tanh_fast(a.y + b.y) * sW2[c*FE + 4*j + 1]
               + tanh_fast(a.z + b.z) * sW2[c*FE + 4*j + 2]
               + tanh_fast(a.w + b.w) * sW2[c*FE + 4*j + 3];
        }
        lg[c] = l;
    }

    float mx = lg[0];
    #pragma unroll
    for (int c = 1; c < CC; ++c) mx = fmaxf(mx, lg[c]);
    float w[CC];
    float sum = 0.f;
    #pragma unroll
    for (int c = 0; c < CC; ++c) { w[c] = expf(lg[c] - mx); sum += w[c]; }
    const float inv = 1.f / sum;

    const int slot = atomicAdd(&g_deg[p*NN + d], 1);
    if (slot < SLOTS) {
        float* rec = g_bkt + ((size_t)(p*NN + d)*SLOTS + slot)*8;
        *(float4*)(rec)     = make_float4(__int_as_float(s),
                                          w[0]*inv, w[1]*inv, w[2]*inv);
        *(float4*)(rec + 4) = make_float4(w[3]*inv, w[4]*inv, 0.f, 0.f);
    }
}

// ---------------------------------------------------------------------------
// aggr: thread = (node, class, float4-chunk). acc = P; loop bucket records,
// gather Y[src] coalesced; h = tanh(acc) written as tf32 into g_H.
// ---------------------------------------------------------------------------
__global__ __launch_bounds__(256) void aggr_kernel()
{
    const int p = blockIdx.z;
    const int idx = blockIdx.x*256 + threadIdx.x;
    if (idx >= NN*80) return;
    const int n   = idx / 80;
    const int rem = idx % 80;
    const int c   = rem >> 4;
    const int qd  = rem & 15;

    const size_t pbase = (((size_t)p*NN + n)*CC + c)*FN + qd*4;
    float4 acc = *(const float4*)(g_P + pbase);

    const int deg = min(g_deg[p*NN + n], SLOTS);
    const float4* rec = (const float4*)(g_bkt + (size_t)(p*NN + n)*SLOTS*8);

    for (int i = 0; i < deg; ++i) {
        const float4 r0 = rec[2*i];
        const int src = __float_as_int(r0.x);
        float wv;
        if (c == 0)      wv = r0.y;
        else if (c == 1) wv = r0.z;
        else if (c == 2) wv = r0.w;
        else {
            const float4 r1 = rec[2*i + 1];
            wv = (c == 3) ? r1.x : r1.y;
        }
        const float4 y = *(const float4*)(g_Y + (((size_t)p*NN + src)*CC + c)*FN + qd*4);
        acc.x += wv*y.x; acc.y += wv*y.y; acc.z += wv*y.z; acc.w += wv*y.w;
    }

    uint4 t;
    t.x = f2tf32(tanh_fast(acc.x));
    t.y = f2tf32(tanh_fast(acc.y));
    t.z = f2tf32(tanh_fast(acc.z));
    t.w = f2tf32(tanh_fast(acc.w));
    *(uint4*)(g_H + pbase) = t;
}

// ---------------------------------------------------------------------------
// G2: out = tanh(H . W2^T + b2), H already tf32. 128 nodes/block.
// ---------------------------------------------------------------------------
#define HST 68
#define W2T 68

__global__ __launch_bounds__(256, 2) void g2_kernel(
    const float* __restrict__ bn2, float* __restrict__ out)
{
    extern __shared__ __align__(16) uint smem_u[];
    uint*  HS  = smem_u;
    uint*  W2S = HS + 128*HST;
    float* sb2 = (float*)(W2S + 64*W2T);

    const int c = blockIdx.y, p = blockIdx.z, tid = threadIdx.x;
    const int n0 = blockIdx.x * 128;
    const int pc = p*CC + c;

    const uint* w2 = g_W2t + (size_t)pc*64*64;
    for (int i = tid; i < 64*16; i += 256) {
        const int g = i >> 4, j = i & 15;
        *(uint4*)&W2S[g*W2T + j*4] = *(const uint4*)&w2[g*64 + j*4];
    }
    if (tid < FN) sb2[tid] = bn2[pc*FN + tid];

    for (int i = tid; i < 128*16; i += 256) {
        const int r = i >> 4, f4 = i & 15;
        const int n = n0 + r;
        uint4 t = make_uint4(0, 0, 0, 0);
        if (n < NN)
            t = *(const uint4*)(g_H + (((size_t)p*NN + n)*CC + c)*FN + f4*4);
        const int ks = f4 >> 1;
        uint* b = &HS[r*HST + ks*8 + (f4 & 1)];
        b[0] = t.x; b[2] = t.y; b[4] = t.z; b[6] = t.w;
    }
    __syncthreads();

    const int warp = tid >> 5, lane = tid & 31;
    const int rowBase = (warp & 3) * 32;
    const int colBase = (warp >> 2) * 32;
    const int r  = lane >> 2;
    const int kk = lane & 3;

    float acc[2][4][4];
    #pragma unroll
    for (int mt = 0; mt < 2; ++mt)
        #pragma unroll
        for (int nt = 0; nt < 4; ++nt)
            #pragma unroll
            for (int q = 0; q < 4; ++q) acc[mt][nt][q] = 0.f;

    #pragma unroll 1
    for (int ks = 0; ks < 8; ++ks) {
        uint a[2][4];
        #pragma unroll
        for (int mt = 0; mt < 2; ++mt) {
            const int rb = rowBase + mt*16;
            const uint2 lo = *(const uint2*)&HS[(rb + r    )*HST + ks*8 + 2*kk];
            const uint2 hi = *(const uint2*)&HS[(rb + r + 8)*HST + ks*8 + 2*kk];
            a[mt][0] = lo.x; a[mt][1] = hi.x; a[mt][2] = lo.y; a[mt][3] = hi.y;
        }
        #pragma unroll
        for (int nt = 0; nt < 4; ++nt) {
            const uint2 b = *(const uint2*)&W2S[(colBase + nt*8 + r)*W2T + ks*8 + 2*kk];
            mma_tf32(acc[0][nt], a[0], b.x, b.y);
            mma_tf32(acc[1][nt], a[1], b.x, b.y);
        }
    }

    #pragma unroll
    for (int mt = 0; mt < 2; ++mt) {
        #pragma unroll
        for (int half = 0; half < 2; ++half) {
            const int n = n0 + rowBase + mt*16 + r + half*8;
            if (n >= NN) continue;
            float* op = out + (((size_t)p*NN + n)*CC + c)*FN;
            #pragma unroll
            for (int nt = 0; nt < 4; ++nt) {
                const int g = colBase + nt*8 + kk*2;
                float2 v;
                v.x = tanhf(acc[mt][nt][half*2 + 0] + sb2[g]);
                v.y = tanhf(acc[mt][nt][half*2 + 1] + sb2[g+1]);
                *(float2*)(op + g) = v;
            }
        }
    }
}

extern "C" void kernel_launch(void* const* d_in, const int* in_sizes, int n_in,
                              void* d_out, int out_size) {
    const float* x   = (const float*)d_in[0];
    const void*  ei  = d_in[1];
    const float* We1 = (const float*)d_in[2];
    const float* be1 = (const float*)d_in[3];
    const float* We2 = (const float*)d_in[4];
    const float* be2 = (const float*)d_in[5];
    const float* Wn1 = (const float*)d_in[6];
    const float* bn1 = (const float*)d_in[7];
    const float* Wn2 = (const float*)d_in[8];
    const float* bn2 = (const float*)d_in[9];
    float* out = (float*)d_out;

    const int smem1 = (128*XST + 160*WST)*4 + 160*4;   // 88192 B
    const int smem2 = (128*HST + 64*W2T)*4 + 64*4;     // 52480 B
    cudaFuncSetAttribute(g1_kernel,
                         cudaFuncAttributeMaxDynamicSharedMemorySize, smem1);
    cudaFuncSetAttribute(g2_kernel,
                         cudaFuncAttributeMaxDynamicSharedMemorySize, smem2);

    wprep_kernel<<<PP*CC, 256>>>(We1, Wn1, Wn2);
    zero_deg_kernel<<<(PP*NN + 255)/256, 256>>>();

    dim3 gg((NN + 127)/128, CC, PP);
    g1_kernel<<<gg, 256, smem1>>>(x, be1, bn1);

    dim3 ge(EE/256, PP);
    gate_kernel<<<ge, 256>>>(ei, We2, be2);

    dim3 ga((NN*80 + 255)/256, 1, PP);
    aggr_kernel<<<ga, 256>>>();

    g2_kernel<<<gg, 256, smem2>>>(bn2, out);
}

// round 15
// speedup vs baseline: 1.1126x; 1.0904x over previous
#include <cuda_runtime.h>
#include <math.h>

#define PP 3
#define NN 50000
#define EE 256000
#define CC 5
#define FF 68
#define FE 16
#define FN 64
#define F2 (2*FF)   // 136
#define SLOTS 32

typedef unsigned int uint;

__device__ __forceinline__ float tanh_fast(float x) {
    float y; asm("tanh.approx.f32 %0, %1;" : "=f"(y) : "f"(x)); return y;
}
__device__ __forceinline__ uint f2tf32(float v) {
    uint t; asm("cvt.rna.tf32.f32 %0, %1;" : "=r"(t) : "f"(v)); return t;
}
__device__ __forceinline__ void mma_tf32(float* c, const uint* a, uint b0, uint b1) {
    asm volatile("mma.sync.aligned.m16n8k8.row.col.f32.tf32.tf32.f32 "
        "{%0,%1,%2,%3}, {%4,%5,%6,%7}, {%8,%9}, {%0,%1,%2,%3};"
        : "+f"(c[0]), "+f"(c[1]), "+f"(c[2]), "+f"(c[3])
        : "r"(a[0]), "r"(a[1]), "r"(a[2]), "r"(a[3]), "r"(b0), "r"(b1));
}

// Scratch. A/B node-major [p][n][c][g] (gate reads all classes of a node).
// P/Y/H CLASS-MAJOR [p][c][n][g]: every producer/consumer runs at fixed c,
// so consecutive nodes become 256B-contiguous rows (DRAM/L2 locality).
__device__ __align__(16) float g_A[(size_t)PP*NN*CC*FE];         // 48 MB
__device__ __align__(16) float g_B[(size_t)PP*NN*CC*FE];         // 48 MB
__device__ __align__(16) float g_P[(size_t)PP*CC*NN*FN];         // 192 MB
__device__ __align__(16) float g_Y[(size_t)PP*CC*NN*FN];         // 192 MB
__device__ __align__(16) uint  g_H[(size_t)PP*CC*NN*FN];         // 192 MB (tf32)
__device__ __align__(16) float g_bkt[(size_t)PP*NN*SLOTS*8];     // 154 MB
__device__ int g_deg[PP*NN];
// Pre-transposed, tf32, k-interleaved weights
__device__ __align__(16) uint g_W1t[(size_t)PP*CC*160*72];
__device__ __align__(16) uint g_W2t[(size_t)PP*CC*64*64];

__global__ void zero_deg_kernel() {
    const int i = blockIdx.x*blockDim.x + threadIdx.x;
    if (i < PP*NN) g_deg[i] = 0;
}

// ---------------------------------------------------------------------------
// wprep: fused+transposed tf32 weight images, k-interleaved (k0,k4,k1,k5,...)
// ---------------------------------------------------------------------------
__global__ __launch_bounds__(256) void wprep_kernel(
    const float* __restrict__ We1, const float* __restrict__ Wn1,
    const float* __restrict__ Wn2)
{
    const int pc = blockIdx.x;
    const size_t eoff = (size_t)pc*FE*F2;
    const size_t noff = (size_t)pc*FN*F2;

    uint* w1 = g_W1t + (size_t)pc*160*72;
    for (int i = threadIdx.x; i < 160*72; i += blockDim.x) {
        const int g = i / 72, kp = i % 72;
        const int ks = kp >> 3, pos = kp & 7;
        const int k = ks*8 + (pos >> 1) + (pos & 1)*4;
        float v = 0.f;
        if (k < FF) {
            if (g < 16)      v = We1[eoff + (size_t)g*F2 + k];
            else if (g < 32) v = We1[eoff + (size_t)(g-16)*F2 + FF + k];
            else if (g < 96) v = Wn1[noff + (size_t)(g-32)*F2 + k];
            else             v = Wn1[noff + (size_t)(g-96)*F2 + FF + k];
        }
        w1[i] = f2tf32(v);
    }

    uint* w2 = g_W2t + (size_t)pc*64*64;
    const float* Wn2p = Wn2 + (size_t)pc*FN*FN;
    for (int i = threadIdx.x; i < 64*64; i += blockDim.x) {
        const int g = i >> 6, kp = i & 63;
        const int ks = kp >> 3, pos = kp & 7;
        const int k = ks*8 + (pos >> 1) + (pos & 1)*4;
        w2[i] = f2tf32(Wn2p[(size_t)g*FN + k]);
    }
}

// ---------------------------------------------------------------------------
// G1: [A|B|P|Y](160) = x(68) . Wf^T per (p,c), tf32 MMA. 128 nodes/block.
// ---------------------------------------------------------------------------
#define XST 76
#define WST 76

__global__ __launch_bounds__(256, 2) void g1_kernel(
    const float* __restrict__ x,
    const float* __restrict__ be1, const float* __restrict__ bn1)
{
    extern __shared__ __align__(16) uint smem_u[];
    uint*  XS    = smem_u;
    uint*  WS    = XS + 128*XST;
    float* sbias = (float*)(WS + 160*WST);

    const int c = blockIdx.y, p = blockIdx.z, tid = threadIdx.x;
    const int n0 = blockIdx.x * 128;
    const int pc = p*CC + c;

    const uint* w1 = g_W1t + (size_t)pc*160*72;
    for (int i = tid; i < 160*18; i += 256) {
        const int g = i / 18, j = i % 18;
        *(uint4*)&WS[g*WST + j*4] = *(const uint4*)&w1[g*72 + j*4];
    }
    for (int g = tid; g < 160; g += 256) {
        float b = 0.f;
        if (g < 16)                 b = be1[pc*FE + g];
        else if (g >= 32 && g < 96) b = bn1[pc*FN + (g-32)];
        sbias[g] = b;
    }
    for (int i = tid; i < 128*17; i += 256) {
        const int r = i / 17, f4 = i % 17;
        const int n = n0 + r;
        float4 v = make_float4(0.f, 0.f, 0.f, 0.f);
        if (n < NN)
            v = *(const float4*)(x + (((size_t)p*NN + n)*CC + c)*FF + f4*4);
        const int ks = f4 >> 1;
        uint* b = &XS[r*XST + ks*8 + (f4 & 1)];
        b[0] = f2tf32(v.x); b[2] = f2tf32(v.y);
        b[4] = f2tf32(v.z); b[6] = f2tf32(v.w);
    }
    for (int i = tid; i < 128*4; i += 256) {
        const int r = i >> 2, j = i & 3;
        XS[r*XST + 64 + 2*j + 1] = 0;
    }
    __syncthreads();

    const int warp = tid >> 5, lane = tid & 31;
    const int rowBase = (warp & 3) * 32;
    const int colBase = (warp >> 2) * 80;
    const int r  = lane >> 2;
    const int kk = lane & 3;

    float acc[2][10][4];
    #pragma unroll
    for (int mt = 0; mt < 2; ++mt)
        #pragma unroll
        for (int nt = 0; nt < 10; ++nt)
            #pragma unroll
            for (int q = 0; q < 4; ++q) acc[mt][nt][q] = 0.f;

    #pragma unroll 1
    for (int ks = 0; ks < 9; ++ks) {
        uint a[2][4];
        #pragma unroll
        for (int mt = 0; mt < 2; ++mt) {
            const int rb = rowBase + mt*16;
            const uint2 lo = *(const uint2*)&XS[(rb + r    )*XST + ks*8 + 2*kk];
            const uint2 hi = *(const uint2*)&XS[(rb + r + 8)*XST + ks*8 + 2*kk];
            a[mt][0] = lo.x; a[mt][1] = hi.x; a[mt][2] = lo.y; a[mt][3] = hi.y;
        }
        #pragma unroll
        for (int nt = 0; nt < 10; ++nt) {
            const uint2 b = *(const uint2*)&WS[(colBase + nt*8 + r)*WST + ks*8 + 2*kk];
            mma_tf32(acc[0][nt], a[0], b.x, b.y);
            mma_tf32(acc[1][nt], a[1], b.x, b.y);
        }
    }

    const size_t pnc = (size_t)p*NN;        // A/B: [p][n][c][g]
    const size_t pcn = (size_t)pc*NN;       // P/Y: [p][c][n][g]
    #pragma unroll
    for (int mt = 0; mt < 2; ++mt) {
        #pragma unroll
        for (int half = 0; half < 2; ++half) {
            const int n = n0 + rowBase + mt*16 + r + half*8;
            if (n >= NN) continue;
            const size_t baseAB = (pnc + n)*CC + c;
            const size_t basePY = (pcn + n)*FN;
            #pragma unroll
            for (int nt = 0; nt < 10; ++nt) {
                const int g = colBase + nt*8 + kk*2;
                float2 v;
                v.x = acc[mt][nt][half*2 + 0] + sbias[g];
                v.y = acc[mt][nt][half*2 + 1] + sbias[g+1];
                if (g < 16)      *(float2*)(g_A + baseAB*FE + g)      = v;
                else if (g < 32) *(float2*)(g_B + baseAB*FE + (g-16)) = v;
                else if (g < 96) *(float2*)(g_P + basePY + (g-32))    = v;
                else             *(float2*)(g_Y + basePY + (g-96))    = v;
            }
        }
    }
}

// ---------------------------------------------------------------------------
// gate: per edge, compute softmax class weights; write one 32B bucket record
// {src, w0..w4} into dst's slot list.
// ---------------------------------------------------------------------------
__global__ __launch_bounds__(256) void gate_kernel(
    const void* __restrict__ ei,
    const float* __restrict__ We2, const float* __restrict__ be2)
{
    __shared__ float sW2[CC*FE];
    __shared__ float sb2[CC];

    const int p = blockIdx.y;
    for (int i = threadIdx.x; i < CC*FE; i += blockDim.x)
        sW2[i] = We2[p*CC*FE + i];
    if (threadIdx.x < CC) sb2[threadIdx.x] = be2[p*CC + threadIdx.x];
    __syncthreads();

    const long long* q = (const long long*)ei;
    int ok = 1;
    #pragma unroll
    for (int i = 0; i < 16; ++i) {
        const long long v = q[i];
        ok &= (v >= 0) && (v < NN);
    }

    const long long* ei64 = (const long long*)ei;
    const int*       ei32 = (const int*)ei;
    const size_t base = (size_t)p*2*EE;

    const int e = blockIdx.x*blockDim.x + threadIdx.x;
    int s, d;
    if (ok) {
        s = (int)ei64[base + e];
        d = (int)ei64[base + EE + e];
    } else {
        s = ei32[base + e];
        d = ei32[base + EE + e];
    }

    const float4* Ad = (const float4*)(g_A + ((size_t)p*NN + d)*(CC*FE));
    const float4* Bs = (const float4*)(g_B + ((size_t)p*NN + s)*(CC*FE));

    float lg[CC];
    #pragma unroll
    for (int c = 0; c < CC; ++c) {
        float l = sb2[c];
        #pragma unroll
        for (int j = 0; j < 4; ++j) {
            const float4 a = Ad[c*4 + j];
            const float4 b = Bs[c*4 + j];
            l += tanh_fast(a.x + b.x) * sW2[c*FE + 4*j + 0]
               + tanh_fast(a.y + b.y) * sW2[c*FE + 4*j + 1]
               + tanh_fast(a.z + b.z) * sW2[c*FE + 4*j + 2]
               + tanh_fast(a.w + b.w) * sW2[c*FE + 4*j + 3];
        }
        lg[c] = l;
    }

    float mx = lg[0];
    #pragma unroll
    for (int c = 1; c < CC; ++c) mx = fmaxf(mx, lg[c]);
    float w[CC];
    float sum = 0.f;
    #pragma unroll
    for (int c = 0; c < CC; ++c) { w[c] = expf(lg[c] - mx); sum += w[c]; }
    const float inv = 1.f / sum;

    const int slot = atomicAdd(&g_deg[p*NN + d], 1);
    if (slot < SLOTS) {
        float* rec = g_bkt + ((size_t)(p*NN + d)*SLOTS + slot)*8;
        *(float4*)(rec)     = make_float4(__int_as_float(s),
                                          w[0]*inv, w[1]*inv, w[2]*inv);
        *(float4*)(rec + 4) = make_float4(w[3]*inv, w[4]*inv, 0.f, 0.f);
    }
}

// ---------------------------------------------------------------------------
// aggr: thread = (node, float4-chunk) at fixed class (blockIdx.y).
// acc = P; loop bucket records, gather Y[src] coalesced;
// h = tanh(acc) written as tf32 into g_H. All P/H accesses warp-contiguous.
// ---------------------------------------------------------------------------
__global__ __launch_bounds__(256) void aggr_kernel()
{
    const int p = blockIdx.z;
    const int c = blockIdx.y;
    const int idx = blockIdx.x*256 + threadIdx.x;
    if (idx >= NN*16) return;
    const int n  = idx >> 4;
    const int qd = idx & 15;

    const size_t pcn = (size_t)(p*CC + c)*NN;
    const size_t pbase = (pcn + n)*FN + qd*4;
    float4 acc = *(const float4*)(g_P + pbase);

    const int deg = min(g_deg[p*NN + n], SLOTS);
    const float4* rec = (const float4*)(g_bkt + (size_t)(p*NN + n)*SLOTS*8);

    for (int i = 0; i < deg; ++i) {
        const float4 r0 = rec[2*i];
        const int src = __float_as_int(r0.x);
        float wv;
        if (c == 0)      wv = r0.y;
        else if (c == 1) wv = r0.z;
        else if (c == 2) wv = r0.w;
        else {
            const float4 r1 = rec[2*i + 1];
            wv = (c == 3) ? r1.x : r1.y;
        }
        const float4 y = *(const float4*)(g_Y + (pcn + src)*FN + qd*4);
        acc.x += wv*y.x; acc.y += wv*y.y; acc.z += wv*y.z; acc.w += wv*y.w;
    }

    uint4 t;
    t.x = f2tf32(tanh_fast(acc.x));
    t.y = f2tf32(tanh_fast(acc.y));
    t.z = f2tf32(tanh_fast(acc.z));
    t.w = f2tf32(tanh_fast(acc.w));
    *(uint4*)(g_H + pbase) = t;
}

// ---------------------------------------------------------------------------
// G2: out = tanh(H . W2^T + b2), H already tf32 class-major. 128 nodes/block.
// ---------------------------------------------------------------------------
#define HST 68
#define W2T 68

__global__ __launch_bounds__(256, 2) void g2_kernel(
    const float* __restrict__ bn2, float* __restrict__ out)
{
    extern __shared__ __align__(16) uint smem_u[];
    uint*  HS  = smem_u;
    uint*  W2S = HS + 128*HST;
    float* sb2 = (float*)(W2S + 64*W2T);

    const int c = blockIdx.y, p = blockIdx.z, tid = threadIdx.x;
    const int n0 = blockIdx.x * 128;
    const int pc = p*CC + c;

    const uint* w2 = g_W2t + (size_t)pc*64*64;
    for (int i = tid; i < 64*16; i += 256) {
        const int g = i >> 4, j = i & 15;
        *(uint4*)&W2S[g*W2T + j*4] = *(const uint4*)&w2[g*64 + j*4];
    }
    if (tid < FN) sb2[tid] = bn2[pc*FN + tid];

    const size_t pcn = (size_t)pc*NN;
    for (int i = tid; i < 128*16; i += 256) {
        const int r = i >> 4, f4 = i & 15;
        const int n = n0 + r;
        uint4 t = make_uint4(0, 0, 0, 0);
        if (n < NN)
            t = *(const uint4*)(g_H + (pcn + n)*FN + f4*4);
        const int ks = f4 >> 1;
        uint* b = &HS[r*HST + ks*8 + (f4 & 1)];
        b[0] = t.x; b[2] = t.y; b[4] = t.z; b[6] = t.w;
    }
    __syncthreads();

    const int warp = tid >> 5, lane = tid & 31;
    const int rowBase = (warp & 3) * 32;
    const int colBase = (warp >> 2) * 32;
    const int r  = lane >> 2;
    const int kk = lane & 3;

    float acc[2][4][4];
    #pragma unroll
    for (int mt = 0; mt < 2; ++mt)
        #pragma unroll
        for (int nt = 0; nt < 4; ++nt)
            #pragma unroll
            for (int q = 0; q < 4; ++q) acc[mt][nt][q] = 0.f;

    #pragma unroll 1
    for (int ks = 0; ks < 8; ++ks) {
        uint a[2][4];
        #pragma unroll
        for (int mt = 0; mt < 2; ++mt) {
            const int rb = rowBase + mt*16;
            const uint2 lo = *(const uint2*)&HS[(rb + r    )*HST + ks*8 + 2*kk];
            const uint2 hi = *(const uint2*)&HS[(rb + r + 8)*HST + ks*8 + 2*kk];
            a[mt][0] = lo.x; a[mt][1] = hi.x; a[mt][2] = lo.y; a[mt][3] = hi.y;
        }
        #pragma unroll
        for (int nt = 0; nt < 4; ++nt) {
            const uint2 b = *(const uint2*)&W2S[(colBase + nt*8 + r)*W2T + ks*8 + 2*kk];
            mma_tf32(acc[0][nt], a[0], b.x, b.y);
            mma_tf32(acc[1][nt], a[1], b.x, b.y);
        }
    }

    #pragma unroll
    for (int mt = 0; mt < 2; ++mt) {
        #pragma unroll
        for (int half = 0; half < 2; ++half) {
            const int n = n0 + rowBase + mt*16 + r + half*8;
            if (n >= NN) continue;
            float* op = out + (((size_t)p*NN + n)*CC + c)*FN;
            #pragma unroll
            for (int nt = 0; nt < 4; ++nt) {
                const int g = colBase + nt*8 + kk*2;
                float2 v;
                v.x = tanhf(acc[mt][nt][half*2 + 0] + sb2[g]);
                v.y = tanhf(acc[mt][nt][half*2 + 1] + sb2[g+1]);
                *(float2*)(op + g) = v;
            }
        }
    }
}

extern "C" void kernel_launch(void* const* d_in, const int* in_sizes, int n_in,
                              void* d_out, int out_size) {
    const float* x   = (const float*)d_in[0];
    const void*  ei  = d_in[1];
    const float* We1 = (const float*)d_in[2];
    const float* be1 = (const float*)d_in[3];
    const float* We2 = (const float*)d_in[4];
    const float* be2 = (const float*)d_in[5];
    const float* Wn1 = (const float*)d_in[6];
    const float* bn1 = (const float*)d_in[7];
    const float* Wn2 = (const float*)d_in[8];
    const float* bn2 = (const float*)d_in[9];
    float* out = (float*)d_out;

    const int smem1 = (128*XST + 160*WST)*4 + 160*4;   // 88192 B
    const int smem2 = (128*HST + 64*W2T)*4 + 64*4;     // 52480 B
    cudaFuncSetAttribute(g1_kernel,
                         cudaFuncAttributeMaxDynamicSharedMemorySize, smem1);
    cudaFuncSetAttribute(g2_kernel,
                         cudaFuncAttributeMaxDynamicSharedMemorySize, smem2);

    wprep_kernel<<<PP*CC, 256>>>(We1, Wn1, Wn2);
    zero_deg_kernel<<<(PP*NN + 255)/256, 256>>>();

    dim3 gg((NN + 127)/128, CC, PP);
    g1_kernel<<<gg, 256, smem1>>>(x, be1, bn1);

    dim3 ge(EE/256, PP);
    gate_kernel<<<ge, 256>>>(ei, We2, be2);

    dim3 ga((NN*16 + 255)/256, CC, PP);
    aggr_kernel<<<ga, 256>>>();

    g2_kernel<<<gg, 256, smem2>>>(bn2, out);
}